// round 3
// baseline (speedup 1.0000x reference)
#include <cuda_runtime.h>
#include <math.h>

#define Bc 4
#define Lc 32
#define Cc 32
#define Hc 128
#define Wc 128
#define HWc (Hc*Wc)
#define IMG_SLICE (Cc*HWc)

// Internal image buffers, channel-interleaved [B,L,H,W,C].
__device__ float g_imgA[(size_t)Bc*Lc*IMG_SLICE];   // transposed input (slice0 read-only) + ping-pong
__device__ float g_imgB[(size_t)Bc*Lc*IMG_SLICE];   // ping-pong
__device__ float g_imgF[(size_t)Bc*Lc*IMG_SLICE];   // finalized slices (HWC, gather sources)
// Flow buffers, planar [B,L,2,H,W]
__device__ float g_flowA[(size_t)Bc*Lc*2*HWc];
__device__ float g_flowB[(size_t)Bc*Lc*2*HWc];
__device__ float g_flowF[(size_t)Bc*Lc*2*HWc];

// ---------------------------------------------------------------------------
// CHW -> HWC transpose of all input image slices.
__global__ void t_chw2hwc(const float* __restrict__ src, float* __restrict__ dst) {
    __shared__ float sm[32][65];
    int tile = blockIdx.x & 255;
    int sl   = blockIdx.x >> 8;
    int pix0 = tile * 64;
    const float* s = src + (size_t)sl * IMG_SLICE;
    float*       d = dst + (size_t)sl * IMG_SLICE;
    int tx = threadIdx.x & 63, ty = threadIdx.x >> 6;
    #pragma unroll
    for (int i = 0; i < 8; i++) {
        int c = ty + i * 4;
        sm[c][tx] = s[c * HWc + pix0 + tx];
    }
    __syncthreads();
    #pragma unroll
    for (int j = 0; j < 2; j++) {
        int u = threadIdx.x + j * 256;
        int p = u >> 3, q = u & 7;
        float4 v = make_float4(sm[4*q+0][p], sm[4*q+1][p], sm[4*q+2][p], sm[4*q+3][p]);
        *(float4*)(d + (size_t)(pix0 + p) * Cc + 4 * q) = v;
    }
}

// Output slice 0 = input images slice 0 (CHW copy).
__global__ void copy_slice0(const float* __restrict__ img, float* __restrict__ out) {
    int i = blockIdx.x * blockDim.x + threadIdx.x;
    const int per = IMG_SLICE / 4;
    const int n = Bc * per;
    if (i >= n) return;
    int b = i / per, r = i % per;
    const float4* s = (const float4*)(img + (size_t)b * Lc * IMG_SLICE) + r;
    float4*       d = (float4*)(out + (size_t)b * Lc * IMG_SLICE) + r;
    *d = *s;
}

// ---------------------------------------------------------------------------
__device__ __forceinline__ void grid_weights(
    int pix, float qfx, float qfy,
    float& w00, float& w01, float& w10, float& w11,
    int& o00, int& o01, int& o10, int& o11)
{
    int h = pix >> 7;
    int w = pix & (Wc - 1);
    float gx = -1.0f + (2.0f / Wc) * ((float)w + 0.5f);
    float gy = -1.0f + (2.0f / Hc) * ((float)h + 0.5f);
    float fx = gx + qfx;
    float t  = fx + 1.0f;
    fx = t - 2.0f * floorf(t * 0.5f) - 1.0f;   // remainder(fx+1,2)-1 (x wrap)
    float fy = gy + qfy;

    float x = (fx + 1.0f) * (Wc * 0.5f) - 0.5f;
    float y = (fy + 1.0f) * (Hc * 0.5f) - 0.5f;
    float x0f = floorf(x), y0f = floorf(y);
    float tx = x - x0f, ty = y - y0f;
    int x0 = (int)x0f, y0 = (int)y0f;
    int x1 = x0 + 1,  y1 = y0 + 1;

    float vx0 = (x0 >= 0 && x0 < Wc) ? 1.0f : 0.0f;
    float vx1 = (x1 >= 0 && x1 < Wc) ? 1.0f : 0.0f;
    float vy0 = (y0 >= 0 && y0 < Hc) ? 1.0f : 0.0f;
    float vy1 = (y1 >= 0 && y1 < Hc) ? 1.0f : 0.0f;

    w00 = (1.0f - tx) * (1.0f - ty) * vx0 * vy0;
    w01 = tx * (1.0f - ty) * vx1 * vy0;
    w10 = (1.0f - tx) * ty * vx0 * vy1;
    w11 = tx * ty * vx1 * vy1;

    int cx0 = min(max(x0, 0), Wc - 1), cx1 = min(max(x1, 0), Wc - 1);
    int cy0 = min(max(y0, 0), Hc - 1), cy1 = min(max(y1, 0), Hc - 1);
    o00 = cy0 * Wc + cx0; o01 = cy0 * Wc + cx1;
    o10 = cy1 * Wc + cx0; o11 = cy1 * Wc + cx1;
}

// ---------------------------------------------------------------------------
// Flow compose (planar). grid = (HW/256, Lp, B).
__global__ void __launch_bounds__(256) compose_flow(int step,
    const float* __restrict__ srcFlow, const float* __restrict__ orgFlow,
    float* __restrict__ finFlow, float* __restrict__ dstFlow)
{
    int pix = blockIdx.x * 256 + threadIdx.x;
    int lp  = blockIdx.y;
    int b   = blockIdx.z;
    int l   = step + lp;

    const float* cf = srcFlow + (size_t)(b * Lc + l) * 2 * HWc;
    float qfx = __ldg(cf + pix);
    float qfy = __ldg(cf + HWc + pix);

    float w00, w01, w10, w11; int o00, o01, o10, o11;
    grid_weights(pix, qfx, qfy, w00, w01, w10, w11, o00, o01, o10, o11);

    const float* pf = (lp == 0) ? (orgFlow + (size_t)(b * Lc) * 2 * HWc)
                   : (lp < step) ? (finFlow + (size_t)(b * Lc + lp) * 2 * HWc)
                                 : (srcFlow + (size_t)(b * Lc + lp) * 2 * HWc);
    float* df = ((l < 2 * step) ? finFlow : dstFlow) + (size_t)(b * Lc + l) * 2 * HWc;

    float s0 = w00 * __ldg(pf + o00) + w01 * __ldg(pf + o01)
             + w10 * __ldg(pf + o10) + w11 * __ldg(pf + o11);
    const float* pf1 = pf + HWc;
    float s1 = w00 * __ldg(pf1 + o00) + w01 * __ldg(pf1 + o01)
             + w10 * __ldg(pf1 + o10) + w11 * __ldg(pf1 + o11);
    df[pix]       = qfx + s0;
    df[HWc + pix] = qfy + s1;
}

// ---------------------------------------------------------------------------
// Image compose, thread-per-pixel, 32 channels/thread, HWC gather.
// grid = (HW/256, Lp, B). Finalized slices write CHW directly into d_out
// (coalesced across lanes); if finHWC, also keep HWC copy for later gathers.
__global__ void __launch_bounds__(256) compose_img2(int step, int finHWC,
    const float* __restrict__ srcImg, const float* __restrict__ orgImg,
    float* __restrict__ finImg,       float* __restrict__ dstImg,
    const float* __restrict__ srcFlow, float* __restrict__ outImg)
{
    int pix = blockIdx.x * 256 + threadIdx.x;
    int lp  = blockIdx.y;
    int b   = blockIdx.z;
    int l   = step + lp;

    const float* cf = srcFlow + (size_t)(b * Lc + l) * 2 * HWc;
    float qfx = __ldg(cf + pix);
    float qfy = __ldg(cf + HWc + pix);

    float w00, w01, w10, w11; int o00, o01, o10, o11;
    grid_weights(pix, qfx, qfy, w00, w01, w10, w11, o00, o01, o10, o11);

    const float* pi = ((lp == 0) ? orgImg : (lp < step) ? finImg : srcImg)
                      + (size_t)(b * Lc + lp) * IMG_SLICE;
    const float* p00 = pi + (size_t)o00 * Cc;
    const float* p01 = pi + (size_t)o01 * Cc;
    const float* p10 = pi + (size_t)o10 * Cc;
    const float* p11 = pi + (size_t)o11 * Cc;

    size_t sliceOff = (size_t)(b * Lc + l) * IMG_SLICE;
    const float* cs = srcImg + sliceOff + (size_t)pix * Cc;

    bool fin = (l < 2 * step);                  // block-uniform
    float* dH = (fin ? finImg : dstImg) + sliceOff + (size_t)pix * Cc;
    float* oC = outImg + sliceOff + pix;

    #pragma unroll
    for (int g = 0; g < 8; g++) {
        int co = g * 4;
        float4 t00 = __ldg((const float4*)(p00 + co));
        float4 t01 = __ldg((const float4*)(p01 + co));
        float4 t10 = __ldg((const float4*)(p10 + co));
        float4 t11 = __ldg((const float4*)(p11 + co));
        float4 cv  = __ldg((const float4*)(cs  + co));

        float4 r;
        r.x = cv.x + w00 * t00.x + w01 * t01.x + w10 * t10.x + w11 * t11.x;
        r.y = cv.y + w00 * t00.y + w01 * t01.y + w10 * t10.y + w11 * t11.y;
        r.z = cv.z + w00 * t00.z + w01 * t01.z + w10 * t10.z + w11 * t11.z;
        r.w = cv.w + w00 * t00.w + w01 * t01.w + w10 * t10.w + w11 * t11.w;

        if (fin) {
            oC[(co + 0) * HWc] = r.x;
            oC[(co + 1) * HWc] = r.y;
            oC[(co + 2) * HWc] = r.z;
            oC[(co + 3) * HWc] = r.w;
            if (finHWC) *(float4*)(dH + co) = r;
        } else {
            *(float4*)(dH + co) = r;
        }
    }
}

// ---------------------------------------------------------------------------
extern "C" void kernel_launch(void* const* d_in, const int* in_sizes, int n_in,
                              void* d_out, int out_size) {
    const float* flows  = (const float*)d_in[0];
    const float* images = (const float*)d_in[1];
    if (n_in >= 2 && in_sizes[0] > in_sizes[1]) {
        const float* tmp = flows; flows = images; images = tmp;
    }
    float* out = (float*)d_out;

    float *iA, *iB, *iF, *fA, *fB, *fF;
    cudaGetSymbolAddress((void**)&iA, g_imgA);
    cudaGetSymbolAddress((void**)&iB, g_imgB);
    cudaGetSymbolAddress((void**)&iF, g_imgF);
    cudaGetSymbolAddress((void**)&fA, g_flowA);
    cudaGetSymbolAddress((void**)&fB, g_flowB);
    cudaGetSymbolAddress((void**)&fF, g_flowF);

    // 1) transpose input images CHW -> HWC into iA
    t_chw2hwc<<<Bc * Lc * 256, 256>>>(images, iA);

    // 2) output slice 0 = input slice 0
    {
        int n = Bc * IMG_SLICE / 4;
        copy_slice0<<<(n + 255) / 256, 256>>>(images, out);
    }

    // 3) log-scan
    const float* sImg  = iA;    float* dImg  = iB;
    const float* sFlow = flows; float* dFlow = fB;
    for (int s = 1; s < Lc; s <<= 1) {
        int Lp = Lc - s;
        dim3 grid(HWc / 256, Lp, Bc);

        if (s < 16) {  // last step's flow output is never consumed
            compose_flow<<<grid, 256>>>(s, sFlow, flows, fF, dFlow);
        }
        int finHWC = (s < 16) ? 1 : 0;  // last step's finalized slices never re-gathered
        compose_img2<<<grid, 256>>>(s, finHWC, sImg, iA, iF, dImg, sFlow, out);

        const float* tI = sImg; sImg = dImg; dImg = (float*)tI;
        if (s == 1) { sFlow = fB; dFlow = fA; }
        else { const float* tF = sFlow; sFlow = dFlow; dFlow = (float*)tF; }
    }
}

// round 5
// speedup vs baseline: 2.4934x; 2.4934x over previous
#include <cuda_runtime.h>
#include <math.h>

#define Bc 4
#define Lc 32
#define Cc 32
#define Hc 128
#define Wc 128
#define HWc (Hc*Wc)
#define IMG_SLICE (Cc*HWc)

// Internal image buffers, channel-interleaved [B,L,H,W,C].
__device__ float g_imgA[(size_t)Bc*Lc*IMG_SLICE];   // transposed input (slice0 read-only) + ping-pong
__device__ float g_imgB[(size_t)Bc*Lc*IMG_SLICE];   // ping-pong
__device__ float g_imgF[(size_t)Bc*Lc*IMG_SLICE];   // finalized slices (HWC gather sources)
// Flow buffers, planar [B,L,2,H,W]
__device__ float g_flowA[(size_t)Bc*Lc*2*HWc];
__device__ float g_flowB[(size_t)Bc*Lc*2*HWc];
__device__ float g_flowF[(size_t)Bc*Lc*2*HWc];

// ---------------------------------------------------------------------------
// CHW -> HWC transpose of all input image slices.
__global__ void t_chw2hwc(const float* __restrict__ src, float* __restrict__ dst) {
    __shared__ float sm[32][65];
    int tile = blockIdx.x & 255;
    int sl   = blockIdx.x >> 8;
    int pix0 = tile * 64;
    const float* s = src + (size_t)sl * IMG_SLICE;
    float*       d = dst + (size_t)sl * IMG_SLICE;
    int tx = threadIdx.x & 63, ty = threadIdx.x >> 6;
    #pragma unroll
    for (int i = 0; i < 8; i++) {
        int c = ty + i * 4;
        sm[c][tx] = s[c * HWc + pix0 + tx];
    }
    __syncthreads();
    #pragma unroll
    for (int j = 0; j < 2; j++) {
        int u = threadIdx.x + j * 256;
        int p = u >> 3, q = u & 7;
        float4 v = make_float4(sm[4*q+0][p], sm[4*q+1][p], sm[4*q+2][p], sm[4*q+3][p]);
        *(float4*)(d + (size_t)(pix0 + p) * Cc + 4 * q) = v;
    }
}

// Output slice 0 = input images slice 0 (CHW copy).
__global__ void copy_slice0(const float* __restrict__ img, float* __restrict__ out) {
    int i = blockIdx.x * blockDim.x + threadIdx.x;
    const int per = IMG_SLICE / 4;
    const int n = Bc * per;
    if (i >= n) return;
    int b = i / per, r = i % per;
    const float4* s = (const float4*)(img + (size_t)b * Lc * IMG_SLICE) + r;
    float4*       d = (float4*)(out + (size_t)b * Lc * IMG_SLICE) + r;
    *d = *s;
}

// ---------------------------------------------------------------------------
// Grid/weight computation — VERBATIM the numerics that passed (R2).
__device__ __forceinline__ void grid_weights(
    int pix, float qfx, float qfy,
    float& w00, float& w01, float& w10, float& w11,
    int& o00, int& o01, int& o10, int& o11)
{
    int h = pix >> 7;
    int w = pix & (Wc - 1);
    float gx = -1.0f + (2.0f / Wc) * ((float)w + 0.5f);
    float gy = -1.0f + (2.0f / Hc) * ((float)h + 0.5f);
    float fx = gx + qfx;
    float t  = fx + 1.0f;
    fx = t - 2.0f * floorf(t * 0.5f) - 1.0f;   // remainder(fx+1,2)-1 (x wrap)
    float fy = gy + qfy;

    float x = (fx + 1.0f) * (Wc * 0.5f) - 0.5f;
    float y = (fy + 1.0f) * (Hc * 0.5f) - 0.5f;
    float x0f = floorf(x), y0f = floorf(y);
    float tx = x - x0f, ty = y - y0f;
    int x0 = (int)x0f, y0 = (int)y0f;
    int x1 = x0 + 1,  y1 = y0 + 1;

    float vx0 = (x0 >= 0 && x0 < Wc) ? 1.0f : 0.0f;
    float vx1 = (x1 >= 0 && x1 < Wc) ? 1.0f : 0.0f;
    float vy0 = (y0 >= 0 && y0 < Hc) ? 1.0f : 0.0f;
    float vy1 = (y1 >= 0 && y1 < Hc) ? 1.0f : 0.0f;

    w00 = (1.0f - tx) * (1.0f - ty) * vx0 * vy0;
    w01 = tx * (1.0f - ty) * vx1 * vy0;
    w10 = (1.0f - tx) * ty * vx0 * vy1;
    w11 = tx * ty * vx1 * vy1;

    int cx0 = min(max(x0, 0), Wc - 1), cx1 = min(max(x1, 0), Wc - 1);
    int cy0 = min(max(y0, 0), Hc - 1), cy1 = min(max(y1, 0), Hc - 1);
    o00 = cy0 * Wc + cx0; o01 = cy0 * Wc + cx1;
    o10 = cy1 * Wc + cx0; o11 = cy1 * Wc + cx1;
}

// ---------------------------------------------------------------------------
// Flow compose (planar). grid = (HW/256, Lp, B) — no div/mod.
__global__ void __launch_bounds__(256) compose_flow(int step,
    const float* __restrict__ srcFlow, const float* __restrict__ orgFlow,
    float* __restrict__ finFlow, float* __restrict__ dstFlow)
{
    int pix = blockIdx.x * 256 + threadIdx.x;
    int lp  = blockIdx.y;
    int b   = blockIdx.z;
    int l   = step + lp;

    const float* cf = srcFlow + (b * Lc + l) * (2 * HWc);
    float qfx = __ldg(cf + pix);
    float qfy = __ldg(cf + HWc + pix);

    float w00, w01, w10, w11; int o00, o01, o10, o11;
    grid_weights(pix, qfx, qfy, w00, w01, w10, w11, o00, o01, o10, o11);

    const float* pf = (lp == 0) ? (orgFlow + (b * Lc) * (2 * HWc))
                   : (lp < step) ? (finFlow + (b * Lc + lp) * (2 * HWc))
                                 : (srcFlow + (b * Lc + lp) * (2 * HWc));
    float* df = ((l < 2 * step) ? finFlow : dstFlow) + (b * Lc + l) * (2 * HWc);

    float s0 = w00 * __ldg(pf + o00) + w01 * __ldg(pf + o01)
             + w10 * __ldg(pf + o10) + w11 * __ldg(pf + o11);
    const float* pf1 = pf + HWc;
    float s1 = w00 * __ldg(pf1 + o00) + w01 * __ldg(pf1 + o01)
             + w10 * __ldg(pf1 + o10) + w11 * __ldg(pf1 + o11);
    df[pix]       = qfx + s0;
    df[HWc + pix] = qfy + s1;
}

// ---------------------------------------------------------------------------
// Image compose. Warp = 4 pixels x 8 channel-groups (1 L1 wavefront per
// pixel-tap). Block = 32 pixels. grid = (HW/32, Lp, B).
// Finalized slices: stage block (32px x 32ch) in smem, store CHW coalesced
// directly into d_out; HWC copy kept only while still a gather source.
__global__ void __launch_bounds__(256) compose_img3(int step, int finHWC,
    const float* __restrict__ srcImg, const float* __restrict__ orgImg,
    float* __restrict__ finImg,       float* __restrict__ dstImg,
    const float* __restrict__ srcFlow, float* __restrict__ outImg)
{
    __shared__ float sm[32 * 33];
    int t   = threadIdx.x;
    int c4  = t & 7;
    int pl  = t >> 3;                 // pixel-local 0..31
    int pix = blockIdx.x * 32 + pl;
    int lp  = blockIdx.y;
    int b   = blockIdx.z;
    int l   = step + lp;

    const float* cf = srcFlow + (b * Lc + l) * (2 * HWc);
    float qfx = __ldg(cf + pix);
    float qfy = __ldg(cf + HWc + pix);

    float w00, w01, w10, w11; int o00, o01, o10, o11;
    grid_weights(pix, qfx, qfy, w00, w01, w10, w11, o00, o01, o10, o11);

    int co = c4 * 4;
    const float* pi = ((lp == 0) ? orgImg : (lp < step) ? finImg : srcImg)
                      + (b * Lc + lp) * IMG_SLICE;
    float4 t00 = __ldg((const float4*)(pi + o00 * Cc + co));
    float4 t01 = __ldg((const float4*)(pi + o01 * Cc + co));
    float4 t10 = __ldg((const float4*)(pi + o10 * Cc + co));
    float4 t11 = __ldg((const float4*)(pi + o11 * Cc + co));

    int sliceOff = (b * Lc + l) * IMG_SLICE;
    int hwcOff   = sliceOff + pix * Cc + co;
    float4 cv = __ldg((const float4*)(srcImg + hwcOff));

    float4 r;
    r.x = cv.x + w00 * t00.x + w01 * t01.x + w10 * t10.x + w11 * t11.x;
    r.y = cv.y + w00 * t00.y + w01 * t01.y + w10 * t10.y + w11 * t11.y;
    r.z = cv.z + w00 * t00.z + w01 * t01.z + w10 * t10.z + w11 * t11.z;
    r.w = cv.w + w00 * t00.w + w01 * t01.w + w10 * t10.w + w11 * t11.w;

    if (l < 2 * step) {                         // finalized (block-uniform)
        if (finHWC) *(float4*)(finImg + hwcOff) = r;
        // stage: sm[pl*33 + c] (stride 33 -> conflict-free both directions)
        int sb = pl * 33 + co;
        sm[sb + 0] = r.x; sm[sb + 1] = r.y; sm[sb + 2] = r.z; sm[sb + 3] = r.w;
        __syncthreads();
        // CHW store: warp (t>>5) handles channels [4w,4w+4), lane = pixel
        int lane = t & 31, wp = t >> 5;
        float* oC = outImg + sliceOff + blockIdx.x * 32 + lane;
        #pragma unroll
        for (int i = 0; i < 4; i++) {
            int ch = wp * 4 + i;
            __stcs(oC + ch * HWc, sm[lane * 33 + ch]);
        }
    } else {
        *(float4*)(dstImg + hwcOff) = r;
    }
}

// ---------------------------------------------------------------------------
extern "C" void kernel_launch(void* const* d_in, const int* in_sizes, int n_in,
                              void* d_out, int out_size) {
    const float* flows  = (const float*)d_in[0];
    const float* images = (const float*)d_in[1];
    if (n_in >= 2 && in_sizes[0] > in_sizes[1]) {
        const float* tmp = flows; flows = images; images = tmp;
    }
    float* out = (float*)d_out;

    float *iA, *iB, *iF, *fA, *fB, *fF;
    cudaGetSymbolAddress((void**)&iA, g_imgA);
    cudaGetSymbolAddress((void**)&iB, g_imgB);
    cudaGetSymbolAddress((void**)&iF, g_imgF);
    cudaGetSymbolAddress((void**)&fA, g_flowA);
    cudaGetSymbolAddress((void**)&fB, g_flowB);
    cudaGetSymbolAddress((void**)&fF, g_flowF);

    // 1) transpose input images CHW -> HWC into iA
    t_chw2hwc<<<Bc * Lc * 256, 256>>>(images, iA);

    // 2) output slice 0 = input slice 0
    {
        int n = Bc * IMG_SLICE / 4;
        copy_slice0<<<(n + 255) / 256, 256>>>(images, out);
    }

    // 3) log-scan
    const float* sImg  = iA;    float* dImg  = iB;
    const float* sFlow = flows; float* dFlow = fB;
    for (int s = 1; s < Lc; s <<= 1) {
        int Lp = Lc - s;

        if (s < 16) {  // last step's flow output is never consumed
            dim3 gf(HWc / 256, Lp, Bc);
            compose_flow<<<gf, 256>>>(s, sFlow, flows, fF, dFlow);
        }
        int finHWC = (s < 16) ? 1 : 0;  // last step's finalized slices never re-gathered
        dim3 gi(HWc / 32, Lp, Bc);
        compose_img3<<<gi, 256>>>(s, finHWC, sImg, iA, iF, dImg, sFlow, out);

        const float* tI = sImg; sImg = dImg; dImg = (float*)tI;
        if (s == 1) { sFlow = fB; dFlow = fA; }
        else { const float* tF = sFlow; sFlow = dFlow; dFlow = (float*)tF; }
    }
}